// round 6
// baseline (speedup 1.0000x reference)
#include <cuda_runtime.h>
#include <cstdint>

#define NIMG   8
#define WID    152
#define HWA    15200
#define KSEL   1000
#define PTN    100
#define NMSN   512
#define NMS_T  0.6f
#define PRE_T  0.05f
#define DWH_CLIP 4.135166556742356f
#define IMGW_M1 1215.0f
#define IMGH_M1 799.0f
#define FULLM  0xFFFFFFFFu

typedef unsigned int       u32;
typedef unsigned long long u64;

__device__ float g_masked[NIMG * HWA];

__device__ __forceinline__ float fsigmoid(float x) {
    return __fdividef(1.0f, 1.0f + __expf(-x));
}

__device__ __forceinline__ float sig4sum(float a, float b, float c, float d) {
    float d1 = 1.0f + __expf(-a);
    float d2 = 1.0f + __expf(-b);
    float d3 = 1.0f + __expf(-c);
    float d4 = 1.0f + __expf(-d);
    float p12 = d1 * d2, p34 = d3 * d4;
    float num = p34 * (d1 + d2) + p12 * (d3 + d4);
    return num * __fdividef(1.0f, p12 * p34);
}

// ---------------------------------------------------------------------------
// Stage A: one warp per anchor (unchanged from R5).
// ---------------------------------------------------------------------------
__global__ void __launch_bounds__(256) stageA(const float* __restrict__ logits,
                                              const float* __restrict__ cent)
{
    int warp = (blockIdx.x << 3) + (threadIdx.x >> 5);
    int lane = threadIdx.x & 31;
    const float4* L4 = (const float4*)logits;
    int b = warp * 64;
    float4 v1 = L4[b + lane];
    float4 v2 = L4[b + 32 + lane];
    float s = sig4sum(v1.x, v1.y, v1.z, v1.w) + sig4sum(v2.x, v2.y, v2.z, v2.w);
#pragma unroll
    for (int o = 16; o; o >>= 1) s += __shfl_xor_sync(FULLM, s, o);
    if (lane == 0) {
        float score = s * (1.0f / 256.0f);
        float m = 0.0f;
        if (score > PRE_T) m = score * fsigmoid(cent[warp]);
        g_masked[warp] = m;
    }
}

// ---------------------------------------------------------------------------
// Stage B: radix select (match-aggregated hist atomics) -> collect (warp-
// aggregated counter) -> hybrid bitonic sort -> decode top-512 -> batch-32
// exact-greedy NMS (~4 rounds, 4 barriers each).
// ---------------------------------------------------------------------------
__global__ void __launch_bounds__(1024) stageB(const float* __restrict__ box_reg,
                                               float* __restrict__ out)
{
    __shared__ __align__(16) unsigned char S[29792];
    u32*    hist      = (u32*)S;                 // 2048 (select only)
    u64*    bufA      = (u64*)S;                 // sort ping
    u64*    bufB      = (u64*)(S + 8192);        // keys + sort pong
    float4* sBox      = (float4*)(S + 16384);    // 512 biased boxes
    float*  sScore    = (float*)(S + 24576);     // 512
    float*  sArea     = (float*)(S + 26624);     // 512
    float4* candBox   = (float4*)(S + 28672);    // 32
    u32*    candSlot  = (u32*)(S + 29184);       // 32
    float*  candArea  = (float*)(S + 29312);     // 32
    float*  candScore = (float*)(S + 29440);     // 32
    u32*    killRow   = (u32*)(S + 29568);       // 32
    u32*    suppWord  = (u32*)(S + 29696);       // 16
    u32*    misc      = (u32*)(S + 29760);       // 8

    const int tid  = threadIdx.x;
    const int lane = tid & 31;
    const int wrp  = tid >> 5;
    const int n    = blockIdx.x;
    const float* mk = g_masked + n * HWA;

    if (tid == 0) { misc[0] = 0u; misc[2] = 0u; misc[3] = KSEL; }
    bufB[tid] = 0ull;
    __syncthreads();

    // ---- 3-round MSB radix select, match-aggregated histogram atomics ----
    const int shifts[3] = {21, 10, 0};
    const int bitsr [3] = {11, 11, 10};
    const int fshft [3] = {32, 21, 10};
#pragma unroll
    for (int r = 0; r < 3; ++r) {
        const int nb = bitsr[r], sh = shifts[r];
        const u32 bmask = (1u << nb) - 1u;
        const int nbins = 1 << nb;
        for (int i = tid; i < nbins; i += 1024) hist[i] = 0u;
        __syncthreads();
        u32 pref = misc[2];
        for (int i = tid; i < HWA; i += 1024) {
            u32 key = __float_as_uint(mk[i]);
            bool ok = (key != 0u) && ((r == 0) || ((key >> fshft[r]) == pref));
            u32 bin = (key >> sh) & bmask;
            u32 ball = __ballot_sync(FULLM, ok);
            if (ok) {
                u32 peers = __match_any_sync(ball, bin);
                if (lane == __ffs(peers) - 1)
                    atomicAdd(&hist[bin], __popc(peers));
            }
        }
        __syncthreads();
        if (tid < 32) {
            int chunk = nbins >> 5;
            int base  = tid * chunk;
            u32 s = 0;
            for (int t = 0; t < chunk; ++t) s += hist[base + t];
            u32 inc = s;
#pragma unroll
            for (int o = 1; o < 32; o <<= 1) {
                u32 v = __shfl_down_sync(FULLM, inc, o);
                if (tid + o < 32) inc += v;
            }
            u32 total = __shfl_sync(FULLM, inc, 0);
            u32 Kc = misc[3];
            if (Kc > total) Kc = (total > 0u) ? total : 1u;
            u32 above = inc - s;
            if (above < Kc && inc >= Kc) {
                u32 cum = above;
                int bsel = base; u32 kr = 1u;
                for (int bb = base + chunk - 1; bb >= base; --bb) {
                    u32 c = hist[bb];
                    if (cum + c >= Kc) { bsel = bb; kr = Kc - cum; break; }
                    cum += c;
                }
                misc[2] = (pref << nb) | (u32)bsel;
                misc[3] = kr;
            }
        }
        __syncthreads();
    }
    const u32 thr = misc[2];
    __syncthreads();

    // ---- collect (warp-aggregated counter): (sqrt bits << 32) | ~idx ----
    for (int i = tid; i < HWA; i += 1024) {
        u32 key = __float_as_uint(mk[i]);
        bool sel = (key != 0u && key >= thr);
        u32 ball = __ballot_sync(FULLM, sel);
        if (sel) {
            int lead = __ffs(ball) - 1;
            u32 base = 0;
            if (lane == lead) base = atomicAdd(&misc[0], (u32)__popc(ball));
            base = __shfl_sync(ball, base, lead);
            u32 pos = base + (u32)__popc(ball & ((1u << lane) - 1u));
            if (pos < 1024u)
                bufB[pos] = ((u64)__float_as_uint(sqrtf(__uint_as_float(key))) << 32)
                          | (0xFFFFFFFFu - (u32)i);
        }
    }
    __syncthreads();
    int C = (int)misc[0]; if (C > 1024) C = 1024;
    int m = C < KSEL ? C : KSEL;
    u64 key = bufB[tid];

    // ---- hybrid bitonic sort, descending ----
#pragma unroll
    for (int k = 2; k <= 32; k <<= 1) {
#pragma unroll
        for (int j = k >> 1; j > 0; j >>= 1) {
            u64 other = __shfl_xor_sync(FULLM, key, j);
            bool keepmax = ((tid & j) == 0) == ((tid & k) == 0);
            key = keepmax ? (key > other ? key : other) : (key < other ? key : other);
        }
    }
    int step = 0;
#pragma unroll
    for (int k = 64; k <= 1024; k <<= 1) {
        for (int j = k >> 1; j >= 32; j >>= 1) {
            u64* buf = (step & 1) ? bufB : bufA;
            buf[tid] = key;
            __syncthreads();
            u64 other = buf[tid ^ j];
            bool keepmax = ((tid & j) == 0) == ((tid & k) == 0);
            key = keepmax ? (key > other ? key : other) : (key < other ? key : other);
            ++step;
        }
#pragma unroll
        for (int j = 16; j > 0; j >>= 1) {
            u64 other = __shfl_xor_sync(FULLM, key, j);
            bool keepmax = ((tid & j) == 0) == ((tid & k) == 0);
            key = keepmax ? (key > other ? key : other) : (key < other ? key : other);
        }
    }

    // ---- decode top-512 boxes (biased form + area) ----
    float4 bt = make_float4(0.f, 0.f, 0.f, 0.f);
    float  areaT = 0.0f;
    if (tid < NMSN) {
        u32 sbits = (u32)(key >> 32);
        float sc = 0.0f;
        if (sbits != 0u) {
            int a  = (int)(0xFFFFFFFFu - (u32)(key & 0xFFFFFFFFull));
            int iy = a / WID;
            int ix = a - iy * WID;
            float cx = (float)ix * 8.0f + 4.5f;
            float cy = (float)iy * 8.0f + 4.5f;
            const float* br = box_reg + (size_t)n * 4 * HWA + a;
            float r0 = br[0], r1 = br[HWA], r2 = br[2 * HWA], r3 = br[3 * HWA];
            float dx = r0 / 10.0f, dy = r1 / 10.0f;
            float dw = fminf(r2 / 5.0f, DWH_CLIP);
            float dh = fminf(r3 / 5.0f, DWH_CLIP);
            float pcx = dx * 65.0f + cx, pcy = dy * 65.0f + cy;
            float pw = expf(dw) * 65.0f, ph = expf(dh) * 65.0f;
            float x1 = fminf(fmaxf(pcx - 0.5f * pw, 0.0f), IMGW_M1);
            float y1 = fminf(fmaxf(pcy - 0.5f * ph, 0.0f), IMGH_M1);
            float x2 = fminf(fmaxf(pcx + 0.5f * pw - 1.0f, 0.0f), IMGW_M1);
            float y2 = fminf(fmaxf(pcy + 0.5f * ph - 1.0f, 0.0f), IMGH_M1);
            bt = make_float4(x1 - 0.5f, y1 - 0.5f, x2 + 0.5f, y2 + 0.5f);
            areaT = (bt.z - bt.x) * (bt.w - bt.y);
            sc = __uint_as_float(sbits);
        }
        sBox[tid]   = bt;
        sScore[tid] = sc;
        sArea[tid]  = areaT;
    }
    __syncthreads();

    // ---- batch-32 exact-greedy NMS ----
    float* outBoxes  = out + (size_t)n * PTN * 4;
    float* outScores = out + (size_t)NIMG * PTN * 4 + (size_t)n * PTN;

    int mA = m < NMSN ? m : NMSN;
    u32 alive = 0u;                 // warp 0, lanes 0..15 own the 512-bit mask
    if (wrp == 0) {
        int lo2 = lane << 5; int r = mA - lo2;
        alive = (lane < 16) ? ((r >= 32) ? FULLM : (r <= 0 ? 0u : ((1u << r) - 1u))) : 0u;
    }

    int p = 0;
    while (true) {
        // -- warp 0: extract first <=32 alive slots, gather their data --
        if (wrp == 0) {
            int cnt = __popc(alive);
            int pre = cnt;
#pragma unroll
            for (int o = 1; o < 32; o <<= 1) {
                int v = __shfl_up_sync(FULLM, pre, o);
                if (lane >= o) pre += v;
            }
            int total = __shfl_sync(FULLM, pre, 31);
            pre -= cnt;                                   // exclusive
            u32 x = alive; int rk = pre;
            while (x && rk < 32) {
                int b = __ffs(x) - 1; x &= x - 1u;
                candSlot[rk] = (u32)((lane << 5) + b);
                ++rk;
            }
            __syncwarp();
            int nc0 = total < 32 ? total : 32;
            if (lane < nc0) {
                int s0 = (int)candSlot[lane];
                candBox[lane]   = sBox[s0];
                candArea[lane]  = sArea[s0];
                candScore[lane] = sScore[s0];
            }
            if (lane == 0) misc[4] = (u32)nc0;
        }
        __syncthreads();                                  // bar1
        int nc = (int)misc[4];
        if (nc == 0) break;

        // -- all warps: kill matrix row for candidate 'wrp' --
        {
            bool k = false;
            if (lane < nc && wrp < nc) {
                float4 bi = candBox[lane];
                float4 bw = candBox[wrp];
                float iw = fminf(bi.z, bw.z) - fmaxf(bi.x, bw.x);
                float ih = fminf(bi.w, bw.w) - fmaxf(bi.y, bw.y);
                float inter = fmaxf(iw, 0.0f) * fmaxf(ih, 0.0f);
                k = inter > NMS_T * (candArea[lane] + candArea[wrp] - inter);
            }
            u32 row = __ballot_sync(FULLM, k);
            if (lane == 0) killRow[wrp] = row;
        }
        __syncthreads();                                  // bar2

        // -- warp 0: sequential-greedy resolution + write picks --
        if (wrp == 0) {
            u32 myrow = killRow[lane];
            u32 acc = 0u, killvec = 0u;
#pragma unroll
            for (int j = 0; j < 32; ++j) {
                u32 rj = __shfl_sync(FULLM, myrow, j);
                if (j < nc && !((killvec >> j) & 1u)) { acc |= (1u << j); killvec |= rj; }
            }
            if ((acc >> lane) & 1u) {
                int rank = __popc(acc & ((1u << lane) - 1u));
                int q = p + rank;
                if (q < PTN) {
                    float4 bf = candBox[lane];
                    outBoxes[q * 4 + 0] = bf.x + 0.5f;
                    outBoxes[q * 4 + 1] = bf.y + 0.5f;
                    outBoxes[q * 4 + 2] = bf.z - 0.5f;
                    outBoxes[q * 4 + 3] = bf.w - 0.5f;
                    outScores[q] = candScore[lane];
                }
            }
            if (lane == 0) misc[5] = acc;
        }
        __syncthreads();                                  // bar3a
        u32 acc = misc[5];
        p += __popc(acc);
        if (p >= PTN) break;

        // -- threads < 512: suppress own box vs accepted candidates --
        if (tid < NMSN) {
            u32 msk = acc;
            bool dead = false;
            while (msk) {
                int j = __ffs(msk) - 1; msk &= msk - 1u;
                float4 bf = candBox[j];
                float aF = candArea[j];
                float iw = fminf(bf.z, bt.z) - fmaxf(bf.x, bt.x);
                float ih = fminf(bf.w, bt.w) - fmaxf(bf.y, bt.y);
                float inter = fmaxf(iw, 0.0f) * fmaxf(ih, 0.0f);
                dead = dead || (inter > NMS_T * (aF + areaT - inter));
            }
            u32 sw = __ballot_sync(FULLM, dead);
            if (lane == 0) suppWord[wrp] = sw;
        }
        __syncthreads();                                  // bar3
        if (wrp == 0 && lane < 16) alive &= ~suppWord[lane];
    }

    if (p > PTN) p = PTN;
    // zero-fill remaining picks (harness poisons d_out)
    for (int q = p + tid; q < PTN; q += 1024) {
        outBoxes[q * 4 + 0] = 0.0f; outBoxes[q * 4 + 1] = 0.0f;
        outBoxes[q * 4 + 2] = 0.0f; outBoxes[q * 4 + 3] = 0.0f;
        outScores[q] = 0.0f;
    }
}

// ---------------------------------------------------------------------------
extern "C" void kernel_launch(void* const* d_in, const int* in_sizes, int n_in,
                              void* d_out, int out_size)
{
    const float* box_regression = (const float*)d_in[0];   // [8,4,100,152]
    const float* centerness     = (const float*)d_in[1];   // [8,1,100,152]
    const float* logits         = (const float*)d_in[3];   // [8,15200,256]
    float* out = (float*)d_out;

    stageA<<<HWA, 256>>>(logits, centerness);
    stageB<<<NIMG, 1024>>>(box_regression, out);
}

// round 7
// speedup vs baseline: 1.0597x; 1.0597x over previous
#include <cuda_runtime.h>
#include <cstdint>

#define NIMG   8
#define WID    152
#define HWA    15200
#define KSEL   512            // top-512 suffices: NMS picks never reach that deep
#define PTN    100
#define NMSN   512
#define NMS_T  0.6f
#define PRE_T  0.05f
#define DWH_CLIP 4.135166556742356f
#define IMGW_M1 1215.0f
#define IMGH_M1 799.0f
#define FULLM  0xFFFFFFFFu

typedef unsigned int       u32;
typedef unsigned long long u64;

__device__ float g_masked[NIMG * HWA];

__device__ __forceinline__ float fsigmoid(float x) {
    return __fdividef(1.0f, 1.0f + __expf(-x));
}

__device__ __forceinline__ float sig4sum(float a, float b, float c, float d) {
    float d1 = 1.0f + __expf(-a);
    float d2 = 1.0f + __expf(-b);
    float d3 = 1.0f + __expf(-c);
    float d4 = 1.0f + __expf(-d);
    float p12 = d1 * d2, p34 = d3 * d4;
    float num = p34 * (d1 + d2) + p12 * (d3 + d4);
    return num * __fdividef(1.0f, p12 * p34);
}

// ---------------------------------------------------------------------------
// Stage A: one warp per anchor (unchanged from R5).
// ---------------------------------------------------------------------------
__global__ void __launch_bounds__(256) stageA(const float* __restrict__ logits,
                                              const float* __restrict__ cent)
{
    int warp = (blockIdx.x << 3) + (threadIdx.x >> 5);
    int lane = threadIdx.x & 31;
    const float4* L4 = (const float4*)logits;
    int b = warp * 64;
    float4 v1 = L4[b + lane];
    float4 v2 = L4[b + 32 + lane];
    float s = sig4sum(v1.x, v1.y, v1.z, v1.w) + sig4sum(v2.x, v2.y, v2.z, v2.w);
#pragma unroll
    for (int o = 16; o; o >>= 1) s += __shfl_xor_sync(FULLM, s, o);
    if (lane == 0) {
        float score = s * (1.0f / 256.0f);
        float m = 0.0f;
        if (score > PRE_T) m = score * fsigmoid(cent[warp]);
        g_masked[warp] = m;
    }
}

// ---------------------------------------------------------------------------
// Stage B (per image, 1024 threads): ONE gmem pass caches 15 keys/thread in
// registers -> 3 radix rounds (smem hist only) -> collect 512 -> 512-key
// hybrid bitonic sort (10 smem stages) -> decode top-512 -> R5 NMS.
//
// smem: [0,8K) hist | sort bufA ; [8K,12K) keys / sort bufB ; [12K,20K) sBox ;
//       [20K,22K) sScore ; [22K,24K) sArea ; [24K,+256) supp[2][32] ; +misc
// ---------------------------------------------------------------------------
__global__ void __launch_bounds__(1024) stageB(const float* __restrict__ box_reg,
                                               float* __restrict__ out)
{
    __shared__ __align__(16) unsigned char S[24864];
    u32*    hist   = (u32*)S;                  // 2048 (select only)
    u64*    bufA   = (u64*)S;                  // sort ping (512)
    u64*    bufB   = (u64*)(S + 8192);         // keys + sort pong (512)
    float4* sBox   = (float4*)(S + 12288);     // 512, biased form
    float*  sScore = (float*)(S + 20480);      // 512
    float*  sArea  = (float*)(S + 22528);      // 512
    u32*    suppS  = (u32*)(S + 24576);        // [2][32]
    u32*    misc   = (u32*)(S + 24832);        // 8 u32

    const int tid  = threadIdx.x;
    const int lane = tid & 31;
    const int wrp  = tid >> 5;
    const int n    = blockIdx.x;
    const float* mk = g_masked + n * HWA;

    // ---- ONE gmem pass: 15 keys per thread into registers ----
    u32 kreg[15];
#pragma unroll
    for (int q = 0; q < 15; ++q) {
        int i = tid + (q << 10);
        kreg[q] = (q < 14 || i < HWA) ? __float_as_uint(mk[i]) : 0u;
    }

    if (tid == 0) { misc[0] = 0u; misc[2] = 0u; misc[3] = KSEL; }
    if (tid < KSEL) bufB[tid] = 0ull;
    suppS[tid & 63] = 0u;
    __syncthreads();

    // ---- 3-round MSB radix select from registers ----
    const int shifts[3] = {21, 10, 0};
    const int bitsr [3] = {11, 11, 10};
    const int fshft [3] = {32, 21, 10};
#pragma unroll
    for (int r = 0; r < 3; ++r) {
        const int nb = bitsr[r], sh = shifts[r];
        const u32 bmask = (1u << nb) - 1u;
        const int nbins = 1 << nb;
        for (int i = tid; i < nbins; i += 1024) hist[i] = 0u;
        __syncthreads();
        u32 pref = misc[2];
#pragma unroll
        for (int q = 0; q < 15; ++q) {
            u32 key = kreg[q];
            if (key != 0u && ((r == 0) || ((key >> fshft[r]) == pref)))
                atomicAdd(&hist[(key >> sh) & bmask], 1u);
        }
        __syncthreads();
        if (tid < 32) {
            int chunk = nbins >> 5;
            int base  = tid * chunk;
            u32 s = 0;
            for (int t = 0; t < chunk; ++t) s += hist[base + t];
            u32 inc = s;
#pragma unroll
            for (int o = 1; o < 32; o <<= 1) {
                u32 v = __shfl_down_sync(FULLM, inc, o);
                if (tid + o < 32) inc += v;
            }
            u32 total = __shfl_sync(FULLM, inc, 0);
            u32 Kc = misc[3];
            if (Kc > total) Kc = (total > 0u) ? total : 1u;
            u32 above = inc - s;
            if (above < Kc && inc >= Kc) {
                u32 cum = above;
                int bsel = base; u32 kr = 1u;
                for (int bb = base + chunk - 1; bb >= base; --bb) {
                    u32 c = hist[bb];
                    if (cum + c >= Kc) { bsel = bb; kr = Kc - cum; break; }
                    cum += c;
                }
                misc[2] = (pref << nb) | (u32)bsel;
                misc[3] = kr;
            }
        }
        __syncthreads();
    }
    const u32 thr = misc[2];
    __syncthreads();

    // ---- collect from registers: (sqrt bits << 32) | ~idx ----
#pragma unroll
    for (int q = 0; q < 15; ++q) {
        u32 key = kreg[q];
        if (key != 0u && key >= thr) {
            u32 gi = (u32)(tid + (q << 10));
            u32 pos = atomicAdd(&misc[0], 1u);
            if (pos < (u32)KSEL)
                bufB[pos] = ((u64)__float_as_uint(sqrtf(__uint_as_float(key))) << 32)
                          | (0xFFFFFFFFu - gi);
        }
    }
    __syncthreads();
    int C = (int)misc[0]; if (C > KSEL) C = KSEL;
    int m = C;
    u64 key = (tid < KSEL) ? bufB[tid] : 0ull;

    // ---- 512-key hybrid bitonic sort (threads < 512), descending ----
#pragma unroll
    for (int k = 2; k <= 32; k <<= 1) {
#pragma unroll
        for (int j = k >> 1; j > 0; j >>= 1) {
            u64 other = __shfl_xor_sync(FULLM, key, j);
            bool keepmax = ((tid & j) == 0) == ((tid & k) == 0);
            key = keepmax ? (key > other ? key : other) : (key < other ? key : other);
        }
    }
    int step = 0;
#pragma unroll
    for (int k = 64; k <= 512; k <<= 1) {
        for (int j = k >> 1; j >= 32; j >>= 1) {
            u64* buf = (step & 1) ? bufB : bufA;
            if (tid < KSEL) buf[tid] = key;
            __syncthreads();
            if (tid < KSEL) {
                u64 other = buf[tid ^ j];
                bool keepmax = ((tid & j) == 0) == ((tid & k) == 0);
                key = keepmax ? (key > other ? key : other) : (key < other ? key : other);
            }
            ++step;
            __syncthreads();
        }
#pragma unroll
        for (int j = 16; j > 0; j >>= 1) {
            u64 other = __shfl_xor_sync(FULLM, key, j);
            bool keepmax = ((tid & j) == 0) == ((tid & k) == 0);
            key = keepmax ? (key > other ? key : other) : (key < other ? key : other);
        }
    }

    // ---- decode top-512 boxes (biased form + area) ----
    float4 bt = make_float4(0.f, 0.f, 0.f, 0.f);
    float  areaT = 0.0f;
    if (tid < NMSN) {
        u32 sbits = (u32)(key >> 32);
        float sc = 0.0f;
        if (sbits != 0u) {
            int a  = (int)(0xFFFFFFFFu - (u32)(key & 0xFFFFFFFFull));
            int iy = a / WID;
            int ix = a - iy * WID;
            float cx = (float)ix * 8.0f + 4.5f;
            float cy = (float)iy * 8.0f + 4.5f;
            const float* br = box_reg + (size_t)n * 4 * HWA + a;
            float r0 = br[0], r1 = br[HWA], r2 = br[2 * HWA], r3 = br[3 * HWA];
            float dx = r0 / 10.0f, dy = r1 / 10.0f;
            float dw = fminf(r2 / 5.0f, DWH_CLIP);
            float dh = fminf(r3 / 5.0f, DWH_CLIP);
            float pcx = dx * 65.0f + cx, pcy = dy * 65.0f + cy;
            float pw = expf(dw) * 65.0f, ph = expf(dh) * 65.0f;
            float x1 = fminf(fmaxf(pcx - 0.5f * pw, 0.0f), IMGW_M1);
            float y1 = fminf(fmaxf(pcy - 0.5f * ph, 0.0f), IMGH_M1);
            float x2 = fminf(fmaxf(pcx + 0.5f * pw - 1.0f, 0.0f), IMGW_M1);
            float y2 = fminf(fmaxf(pcy + 0.5f * ph - 1.0f, 0.0f), IMGH_M1);
            bt = make_float4(x1 - 0.5f, y1 - 0.5f, x2 + 0.5f, y2 + 0.5f);
            areaT = (bt.z - bt.x) * (bt.w - bt.y);
            sc = __uint_as_float(sbits);
        }
        sBox[tid]   = bt;
        sScore[tid] = sc;
        sArea[tid]  = areaT;
    }
    __syncthreads();

    // ---- NMS over top-512 (identical to R5): 1 barrier/round ----
    int mA = m < NMSN ? m : NMSN;
    u32 alive;
    { int lo2 = lane << 5; int r = mA - lo2;
      alive = (r >= 32) ? FULLM : (r <= 0 ? 0u : ((1u << r) - 1u)); }

    float* outBoxes  = out + (size_t)n * PTN * 4;
    float* outScores = out + (size_t)NIMG * PTN * 4 + (size_t)n * PTN;

    int p = 0, rp = 0;
    for (; p < PTN; ) {
        u32 bal = __ballot_sync(FULLM, alive != 0u);
        if (!bal) break;
        int fw = __ffs((int)bal) - 1;
        u32 wv = __shfl_sync(FULLM, alive, fw);
        int f  = (fw << 5) + __ffs((int)wv) - 1;

        u32* sp = suppS + ((rp & 1) << 5);
        if (wrp < (NMSN >> 5)) {
            float4 bf = sBox[f];
            if (tid == 0) {
                outBoxes[p * 4 + 0] = bf.x + 0.5f; outBoxes[p * 4 + 1] = bf.y + 0.5f;
                outBoxes[p * 4 + 2] = bf.z - 0.5f; outBoxes[p * 4 + 3] = bf.w - 0.5f;
                outScores[p] = sScore[f];
            }
            float areaF = sArea[f];
            float iw = fminf(bf.z, bt.z) - fmaxf(bf.x, bt.x);
            float ih = fminf(bf.w, bt.w) - fmaxf(bf.y, bt.y);
            iw = fmaxf(iw, 0.0f); ih = fmaxf(ih, 0.0f);
            float inter = iw * ih;
            bool kill = inter > NMS_T * (areaF + areaT - inter);
            u32 sm = __ballot_sync(FULLM, kill);
            if (lane == 0) sp[wrp] = sm;
        }
        __syncthreads();
        alive &= ~sp[lane];
        ++p; ++rp;
    }

    // zero-fill remaining picks (harness poisons d_out)
    for (int q = p + tid; q < PTN; q += 1024) {
        outBoxes[q * 4 + 0] = 0.0f; outBoxes[q * 4 + 1] = 0.0f;
        outBoxes[q * 4 + 2] = 0.0f; outBoxes[q * 4 + 3] = 0.0f;
        outScores[q] = 0.0f;
    }
}

// ---------------------------------------------------------------------------
extern "C" void kernel_launch(void* const* d_in, const int* in_sizes, int n_in,
                              void* d_out, int out_size)
{
    const float* box_regression = (const float*)d_in[0];   // [8,4,100,152]
    const float* centerness     = (const float*)d_in[1];   // [8,1,100,152]
    const float* logits         = (const float*)d_in[3];   // [8,15200,256]
    float* out = (float*)d_out;

    stageA<<<HWA, 256>>>(logits, centerness);
    stageB<<<NIMG, 1024>>>(box_regression, out);
}

// round 8
// speedup vs baseline: 1.1168x; 1.0538x over previous
#include <cuda_runtime.h>
#include <cstdint>

#define NIMG   8
#define WID    152
#define HWA    15200
#define KSEL   512            // top-512 suffices: NMS picks never go that deep
#define PTN    100
#define NMSN   512
#define NMS_T  0.6f
#define PRE_T  0.05f
#define DWH_CLIP 4.135166556742356f
#define IMGW_M1 1215.0f
#define IMGH_M1 799.0f
#define FULLM  0xFFFFFFFFu

typedef unsigned int       u32;
typedef unsigned long long u64;

__device__ float  g_masked[NIMG * HWA];
__device__ float4 g_sbox [NIMG * NMSN];     // sorted, biased boxes
__device__ float  g_sarea[NIMG * NMSN];
__device__ float  g_sscr [NIMG * NMSN];
__device__ int    g_cnt  [NIMG];

__device__ __forceinline__ float fsigmoid(float x) {
    return __fdividef(1.0f, 1.0f + __expf(-x));
}

__device__ __forceinline__ float sig4sum(float a, float b, float c, float d) {
    float d1 = 1.0f + __expf(-a);
    float d2 = 1.0f + __expf(-b);
    float d3 = 1.0f + __expf(-c);
    float d4 = 1.0f + __expf(-d);
    float p12 = d1 * d2, p34 = d3 * d4;
    float num = p34 * (d1 + d2) + p12 * (d3 + d4);
    return num * __fdividef(1.0f, p12 * p34);
}

// ---------------------------------------------------------------------------
// Stage A: one warp per anchor (unchanged).
// ---------------------------------------------------------------------------
__global__ void __launch_bounds__(256) stageA(const float* __restrict__ logits,
                                              const float* __restrict__ cent)
{
    int warp = (blockIdx.x << 3) + (threadIdx.x >> 5);
    int lane = threadIdx.x & 31;
    const float4* L4 = (const float4*)logits;
    int b = warp * 64;
    float4 v1 = L4[b + lane];
    float4 v2 = L4[b + 32 + lane];
    float s = sig4sum(v1.x, v1.y, v1.z, v1.w) + sig4sum(v2.x, v2.y, v2.z, v2.w);
#pragma unroll
    for (int o = 16; o; o >>= 1) s += __shfl_xor_sync(FULLM, s, o);
    if (lane == 0) {
        float score = s * (1.0f / 256.0f);
        float m = 0.0f;
        if (score > PRE_T) m = score * fsigmoid(cent[warp]);
        g_masked[warp] = m;
    }
}

// ---------------------------------------------------------------------------
// prep (per image, 1024 threads): register-cached radix select -> collect 512
// -> 512-key hybrid bitonic sort (ONE barrier per smem stage) -> decode ->
// write sorted boxes/areas/scores to gmem scratch.
// ---------------------------------------------------------------------------
__global__ void __launch_bounds__(1024) prep(const float* __restrict__ box_reg)
{
    __shared__ __align__(16) unsigned char S[12352];
    u32* hist = (u32*)S;                       // 2048 (select only)
    u64* bufA = (u64*)S;                       // sort ping (512)
    u64* bufB = (u64*)(S + 8192);              // keys + sort pong (512)
    u32* misc = (u32*)(S + 12288);             // 8 u32

    const int tid  = threadIdx.x;
    const int n    = blockIdx.x;
    const float* mk = g_masked + n * HWA;

    // one gmem pass: 15 keys per thread into registers
    u32 kreg[15];
#pragma unroll
    for (int q = 0; q < 15; ++q) {
        int i = tid + (q << 10);
        kreg[q] = (q < 14 || i < HWA) ? __float_as_uint(mk[i]) : 0u;
    }

    if (tid == 0) { misc[0] = 0u; misc[2] = 0u; misc[3] = KSEL; }
    if (tid < KSEL) bufB[tid] = 0ull;
    __syncthreads();

    // 3-round MSB radix select from registers
    const int shifts[3] = {21, 10, 0};
    const int bitsr [3] = {11, 11, 10};
    const int fshft [3] = {32, 21, 10};
#pragma unroll
    for (int r = 0; r < 3; ++r) {
        const int nb = bitsr[r], sh = shifts[r];
        const u32 bmask = (1u << nb) - 1u;
        const int nbins = 1 << nb;
        for (int i = tid; i < nbins; i += 1024) hist[i] = 0u;
        __syncthreads();
        u32 pref = misc[2];
#pragma unroll
        for (int q = 0; q < 15; ++q) {
            u32 key = kreg[q];
            if (key != 0u && ((r == 0) || ((key >> fshft[r]) == pref)))
                atomicAdd(&hist[(key >> sh) & bmask], 1u);
        }
        __syncthreads();
        if (tid < 32) {
            int chunk = nbins >> 5;
            int base  = tid * chunk;
            u32 s = 0;
            for (int t = 0; t < chunk; ++t) s += hist[base + t];
            u32 inc = s;
#pragma unroll
            for (int o = 1; o < 32; o <<= 1) {
                u32 v = __shfl_down_sync(FULLM, inc, o);
                if (tid + o < 32) inc += v;
            }
            u32 total = __shfl_sync(FULLM, inc, 0);
            u32 Kc = misc[3];
            if (Kc > total) Kc = (total > 0u) ? total : 1u;
            u32 above = inc - s;
            if (above < Kc && inc >= Kc) {
                u32 cum = above;
                int bsel = base; u32 kr = 1u;
                for (int bb = base + chunk - 1; bb >= base; --bb) {
                    u32 c = hist[bb];
                    if (cum + c >= Kc) { bsel = bb; kr = Kc - cum; break; }
                    cum += c;
                }
                misc[2] = (pref << nb) | (u32)bsel;
                misc[3] = kr;
            }
        }
        __syncthreads();
    }
    const u32 thr = misc[2];
    __syncthreads();

    // collect: (sqrt bits << 32) | ~idx  (tie -> lower index)
#pragma unroll
    for (int q = 0; q < 15; ++q) {
        u32 key = kreg[q];
        if (key != 0u && key >= thr) {
            u32 gi = (u32)(tid + (q << 10));
            u32 pos = atomicAdd(&misc[0], 1u);
            if (pos < (u32)KSEL)
                bufB[pos] = ((u64)__float_as_uint(sqrtf(__uint_as_float(key))) << 32)
                          | (0xFFFFFFFFu - gi);
        }
    }
    __syncthreads();
    int C = (int)misc[0]; if (C > KSEL) C = KSEL;
    if (tid == 0) g_cnt[n] = C;
    u64 key = (tid < KSEL) ? bufB[tid] : 0ull;

    // 512-key hybrid bitonic sort, descending (one barrier per smem stage)
#pragma unroll
    for (int k = 2; k <= 32; k <<= 1) {
#pragma unroll
        for (int j = k >> 1; j > 0; j >>= 1) {
            u64 other = __shfl_xor_sync(FULLM, key, j);
            bool keepmax = ((tid & j) == 0) == ((tid & k) == 0);
            key = keepmax ? (key > other ? key : other) : (key < other ? key : other);
        }
    }
    int step = 0;
#pragma unroll
    for (int k = 64; k <= 512; k <<= 1) {
        for (int j = k >> 1; j >= 32; j >>= 1) {
            u64* buf = (step & 1) ? bufB : bufA;
            if (tid < KSEL) buf[tid] = key;
            __syncthreads();
            if (tid < KSEL) {
                u64 other = buf[tid ^ j];
                bool keepmax = ((tid & j) == 0) == ((tid & k) == 0);
                key = keepmax ? (key > other ? key : other) : (key < other ? key : other);
            }
            ++step;
        }
        // hazard note: next smem write targets the *other* buffer, whose last
        // read was 2 steps ago, already separated by the barrier above.
#pragma unroll
        for (int j = 16; j > 0; j >>= 1) {
            u64 other = __shfl_xor_sync(FULLM, key, j);
            bool keepmax = ((tid & j) == 0) == ((tid & k) == 0);
            key = keepmax ? (key > other ? key : other) : (key < other ? key : other);
        }
    }
    __syncthreads();   // last smem-stage reads complete before kernel end (no-op safety)

    // decode + write scratch (biased box form + area)
    if (tid < NMSN) {
        u32 sbits = (u32)(key >> 32);
        float4 bt = make_float4(0.f, 0.f, 0.f, 0.f);
        float areaT = 0.0f, sc = 0.0f;
        if (sbits != 0u) {
            int a  = (int)(0xFFFFFFFFu - (u32)(key & 0xFFFFFFFFull));
            int iy = a / WID;
            int ix = a - iy * WID;
            float cx = (float)ix * 8.0f + 4.5f;
            float cy = (float)iy * 8.0f + 4.5f;
            const float* br = box_reg + (size_t)n * 4 * HWA + a;
            float r0 = br[0], r1 = br[HWA], r2 = br[2 * HWA], r3 = br[3 * HWA];
            float dx = r0 / 10.0f, dy = r1 / 10.0f;
            float dw = fminf(r2 / 5.0f, DWH_CLIP);
            float dh = fminf(r3 / 5.0f, DWH_CLIP);
            float pcx = dx * 65.0f + cx, pcy = dy * 65.0f + cy;
            float pw = expf(dw) * 65.0f, ph = expf(dh) * 65.0f;
            float x1 = fminf(fmaxf(pcx - 0.5f * pw, 0.0f), IMGW_M1);
            float y1 = fminf(fmaxf(pcy - 0.5f * ph, 0.0f), IMGH_M1);
            float x2 = fminf(fmaxf(pcx + 0.5f * pw - 1.0f, 0.0f), IMGW_M1);
            float y2 = fminf(fmaxf(pcy + 0.5f * ph - 1.0f, 0.0f), IMGH_M1);
            bt = make_float4(x1 - 0.5f, y1 - 0.5f, x2 + 0.5f, y2 + 0.5f);
            areaT = (bt.z - bt.x) * (bt.w - bt.y);
            sc = __uint_as_float(sbits);
        }
        g_sbox [n * NMSN + tid] = bt;
        g_sarea[n * NMSN + tid] = areaT;
        g_sscr [n * NMSN + tid] = sc;
    }
}

// ---------------------------------------------------------------------------
// nms (per image, 512 threads): R5-proven loop, 16 warps, 1 barrier/round.
// ---------------------------------------------------------------------------
__global__ void __launch_bounds__(512) nms(float* __restrict__ out)
{
    __shared__ __align__(16) float4 sBox[NMSN];
    __shared__ float  sScore[NMSN];
    __shared__ float  sArea[NMSN];
    __shared__ u32    suppS[2 * 16];

    const int tid  = threadIdx.x;
    const int lane = tid & 31;
    const int wrp  = tid >> 5;
    const int n    = blockIdx.x;

    float4 bt    = g_sbox [n * NMSN + tid];
    float  areaT = g_sarea[n * NMSN + tid];
    float  sc    = g_sscr [n * NMSN + tid];
    int    mA    = g_cnt[n];
    sBox[tid]   = bt;
    sScore[tid] = sc;
    sArea[tid]  = areaT;
    __syncthreads();

    // alive mask replicated in each warp: lane l (<16) owns boxes [32l,32l+32)
    u32 alive = 0u;
    if (lane < 16) {
        int lo2 = lane << 5; int r = mA - lo2;
        alive = (r >= 32) ? FULLM : (r <= 0 ? 0u : ((1u << r) - 1u));
    }

    float* outBoxes  = out + (size_t)n * PTN * 4;
    float* outScores = out + (size_t)NIMG * PTN * 4 + (size_t)n * PTN;

    int p = 0, rp = 0;
    for (; p < PTN; ) {
        u32 bal = __ballot_sync(FULLM, alive != 0u);
        if (!bal) break;
        int fw = __ffs((int)bal) - 1;
        u32 wv = __shfl_sync(FULLM, alive, fw);
        int f  = (fw << 5) + __ffs((int)wv) - 1;      // first alive == argmax

        u32* sp = suppS + ((rp & 1) << 4);
        float4 bf = sBox[f];
        if (tid == 0) {
            outBoxes[p * 4 + 0] = bf.x + 0.5f; outBoxes[p * 4 + 1] = bf.y + 0.5f;
            outBoxes[p * 4 + 2] = bf.z - 0.5f; outBoxes[p * 4 + 3] = bf.w - 0.5f;
            outScores[p] = sScore[f];
        }
        float areaF = sArea[f];
        float iw = fminf(bf.z, bt.z) - fmaxf(bf.x, bt.x);
        float ih = fminf(bf.w, bt.w) - fmaxf(bf.y, bt.y);
        iw = fmaxf(iw, 0.0f); ih = fmaxf(ih, 0.0f);
        float inter = iw * ih;
        bool kill = inter > NMS_T * (areaF + areaT - inter);
        u32 sm = __ballot_sync(FULLM, kill);          // self-IoU==1 clears f
        if (lane == 0) sp[wrp] = sm;
        __syncthreads();
        if (lane < 16) alive &= ~sp[lane];
        ++p; ++rp;
    }

    // zero-fill remaining picks (harness poisons d_out)
    for (int q = p + tid; q < PTN; q += 512) {
        outBoxes[q * 4 + 0] = 0.0f; outBoxes[q * 4 + 1] = 0.0f;
        outBoxes[q * 4 + 2] = 0.0f; outBoxes[q * 4 + 3] = 0.0f;
        outScores[q] = 0.0f;
    }
}

// ---------------------------------------------------------------------------
extern "C" void kernel_launch(void* const* d_in, const int* in_sizes, int n_in,
                              void* d_out, int out_size)
{
    const float* box_regression = (const float*)d_in[0];   // [8,4,100,152]
    const float* centerness     = (const float*)d_in[1];   // [8,1,100,152]
    const float* logits         = (const float*)d_in[3];   // [8,15200,256]
    float* out = (float*)d_out;

    stageA<<<HWA, 256>>>(logits, centerness);
    prep<<<NIMG, 1024>>>(box_regression);
    nms<<<NIMG, 512>>>(out);
}